// round 1
// baseline (speedup 1.0000x reference)
#include <cuda_runtime.h>
#include <cuda_bf16.h>
#include <cstddef>

// Problem constants (fixed shapes from reference)
constexpr int B_   = 8;
constexpr int T_   = 32;
constexpr int NN   = 10;     // objects per (b,t)
constexpr int DOBJ = 2048;
constexpr int NV   = 157;    // verbs
constexpr int NC   = 353;    // object classes
constexpr int DE   = 512;    // embedding dim
constexpr int DV   = 2048;   // verb/context dim
constexpr int ROWS = B_ * T_ * NN;       // 2560
constexpr int OUTW = DE + DV;            // 2560

// Scratch (static device globals; no allocation)
__device__ float g_F[(size_t)B_ * NC * DOBJ];   // class-histogram of features (23 MB, active rows only used)
__device__ float g_H[(size_t)B_ * NC * DE];     // F_active @ W (active rows only)
__device__ int   g_cls[ROWS];
__device__ int   g_present[B_ * NC];
__device__ int   g_count[B_ * NC];
__device__ int   g_classlist[B_ * NC];
__device__ int   g_u[B_];
__device__ float g_ctx[B_ * DV];

// ---------------------------------------------------------------------------
// K0: reset presence/count flags
__global__ void k_reset() {
    int i = blockIdx.x * blockDim.x + threadIdx.x;
    if (i < B_ * NC) { g_present[i] = 0; g_count[i] = 0; }
}

// ---------------------------------------------------------------------------
// K1: per-row class decode (last nonzero index; all-zero -> 0)
__global__ void k_cls(const int* __restrict__ obj_id) {
    int gtid = blockIdx.x * blockDim.x + threadIdx.x;
    int warp = gtid >> 5;
    int lane = threadIdx.x & 31;
    if (warp >= ROWS) return;
    const int* row = obj_id + (size_t)warp * NC;
    int best = -1;
    for (int i = lane; i < NC; i += 32)
        if (row[i] != 0) best = i;
    #pragma unroll
    for (int o = 16; o > 0; o >>= 1)
        best = max(best, __shfl_xor_sync(0xffffffffu, best, o));
    int cls = (best < 0) ? 0 : best;
    if (lane == 0) {
        g_cls[warp] = cls;
        int b = warp / (T_ * NN);
        g_present[b * NC + cls] = 1;
        atomicAdd(&g_count[b * NC + cls], 1);
    }
}

// ---------------------------------------------------------------------------
// K2: compact list of present classes per batch (ballot scan)
__global__ void k_unique() {  // grid B_, block 384 (12 warps)
    int b = blockIdx.x;
    int tid = threadIdx.x;
    int w = tid >> 5, lane = tid & 31;
    __shared__ int wc[12], base[12];
    int f = (tid < NC) ? g_present[b * NC + tid] : 0;
    unsigned mask = __ballot_sync(0xffffffffu, f != 0);
    if (lane == 0) wc[w] = __popc(mask);
    __syncthreads();
    if (tid == 0) {
        int run = 0;
        for (int i = 0; i < 12; i++) { base[i] = run; run += wc[i]; }
        g_u[b] = run;
    }
    __syncthreads();
    if (f) {
        int slot = base[w] + __popc(mask & ((1u << lane) - 1u));
        g_classlist[b * NC + slot] = tid;
    }
}

// ---------------------------------------------------------------------------
// KZ: zero only the F rows that will be accumulated this launch
__global__ void k_zeroF() {  // grid (NC, B_), block 256
    int b = blockIdx.y, s = blockIdx.x;
    if (s >= g_u[b]) return;
    int c = g_classlist[b * NC + s];
    float4* p = (float4*)(g_F + ((size_t)b * NC + c) * DOBJ);
    for (int i = threadIdx.x; i < DOBJ / 4; i += 256)
        p[i] = make_float4(0.f, 0.f, 0.f, 0.f);
}

// ---------------------------------------------------------------------------
// K3: scatter-add features into class histogram, smem pre-aggregated per (b,t)
__global__ void k_scatter(const float* __restrict__ feat) {  // grid (T_, B_), block 256
    int b = blockIdx.y, t = blockIdx.x;
    int tid = threadIdx.x;
    __shared__ int c10[NN], ls[NN], uniq[NN];
    __shared__ int m;
    __shared__ float acc[NN * 512];  // 20 KB

    if (tid < NN) c10[tid] = g_cls[(b * T_ + t) * NN + tid];
    __syncthreads();
    if (tid == 0) {
        int mm = 0;
        for (int i = 0; i < NN; i++) {
            int j = 0;
            for (; j < mm; j++) if (uniq[j] == c10[i]) break;
            if (j == mm) uniq[mm++] = c10[i];
            ls[i] = j;
        }
        m = mm;
    }
    __syncthreads();
    int mm = m;
    const float* base = feat + ((size_t)(b * T_ + t) * NN) * DOBJ;

    for (int ch = 0; ch < DOBJ; ch += 512) {
        for (int j = tid; j < mm * 512; j += 256) acc[j] = 0.f;
        __syncthreads();
        for (int n = 0; n < NN; n++) {
            const float* fr = base + (size_t)n * DOBJ + ch;
            float* a = acc + ls[n] * 512;
            #pragma unroll
            for (int e = tid; e < 512; e += 256) a[e] += fr[e];
        }
        __syncthreads();
        for (int j = tid; j < mm * 512; j += 256) {
            int s = j >> 9, e = j & 511;
            atomicAdd(&g_F[((size_t)b * NC + uniq[s]) * DOBJ + ch + e], acc[j]);
        }
        __syncthreads();
    }
}

// ---------------------------------------------------------------------------
// K4: H[b, slot, :] = F[b, class(slot), :] @ W   (active slots only)
// Block = (colchunk of 32, batch). Slot-grouped by 4 to amortize W reads.
constexpr int SG = 4;
__global__ void k_hgemm(const float* __restrict__ W) {  // grid (DE/32=16, B_), block 256
    __shared__ float Fs[SG][DOBJ];     // 32 KB
    __shared__ float red[8][SG][32];   // 4 KB
    int b = blockIdx.y;
    int colg = blockIdx.x * 32;
    int tid = threadIdx.x;
    int col = tid & 31, kg = tid >> 5;   // 8 k-groups of 256
    int u = g_u[b];

    for (int g0 = 0; g0 < u; g0 += SG) {
        int ns = min(SG, u - g0);
        // cooperative load of up to SG F rows (float4)
        for (int j = tid; j < ns * (DOBJ / 4); j += 256) {
            int s = j / (DOBJ / 4), kk = j % (DOBJ / 4);
            int c = g_classlist[b * NC + g0 + s];
            ((float4*)Fs[s])[kk] =
                ((const float4*)(g_F + ((size_t)b * NC + c) * DOBJ))[kk];
        }
        __syncthreads();

        float accv[SG] = {0.f, 0.f, 0.f, 0.f};
        const float* Wp = W + (size_t)(kg * 256) * DE + colg + col;
        for (int k = 0; k < 256; k += 4) {
            int kk = kg * 256 + k;
            float w0 = Wp[(size_t)(k + 0) * DE];
            float w1 = Wp[(size_t)(k + 1) * DE];
            float w2 = Wp[(size_t)(k + 2) * DE];
            float w3 = Wp[(size_t)(k + 3) * DE];
            #pragma unroll
            for (int s = 0; s < SG; s++) {
                float4 f = *(const float4*)&Fs[s][kk];
                accv[s] += f.x * w0 + f.y * w1 + f.z * w2 + f.w * w3;
            }
        }
        #pragma unroll
        for (int s = 0; s < SG; s++) red[kg][s][col] = accv[s];
        __syncthreads();
        if (tid < SG * 32) {
            int s = tid >> 5, c2 = tid & 31;
            float h = 0.f;
            #pragma unroll
            for (int kg2 = 0; kg2 < 8; kg2++) h += red[kg2][s][c2];
            if (s < ns)
                g_H[((size_t)b * NC + g0 + s) * DE + colg + c2] = h;
        }
        __syncthreads();
    }
}

// ---------------------------------------------------------------------------
// Kctx: temporal mean of fm_context  (8 x 2048)
__global__ void k_ctx(const float* __restrict__ fm) {  // grid (DV/256=8, B_), block 256
    int b = blockIdx.y;
    int d = blockIdx.x * 256 + threadIdx.x;
    float s = 0.f;
    #pragma unroll 4
    for (int t = 0; t < T_; t++)
        s += fm[((size_t)(b * T_ + t)) * DV + d];
    g_ctx[b * DV + d] = s * (1.f / T_);
}

// ---------------------------------------------------------------------------
// K5: assemble output rows
__global__ void k_out(const float* __restrict__ Ao2v,
                      const float* __restrict__ bias,
                      float* __restrict__ out) {  // grid (NV, B_), block 256
    int v = blockIdx.x, b = blockIdx.y;
    int tid = threadIdx.x;
    int u = g_u[b];
    float sbv = 0.f;
    float a0 = 0.f, a1 = 0.f;
    for (int s = 0; s < u; s++) {
        int c = g_classlist[b * NC + s];
        float a = Ao2v[(size_t)v * NC + c];
        sbv += a * (float)g_count[b * NC + c];
        const float* Hr = g_H + ((size_t)b * NC + s) * DE;
        a0 += a * Hr[tid];
        a1 += a * Hr[tid + 256];
    }
    const float inv = 1.f / T_;
    float* orow = out + ((size_t)b * NV + v) * OUTW;
    orow[tid]       = (a0 + sbv * bias[tid]) * inv;
    orow[tid + 256] = (a1 + sbv * bias[tid + 256]) * inv;
    const float4* cm = (const float4*)(g_ctx + (size_t)b * DV);
    float4* od = (float4*)(orow + DE);
    #pragma unroll
    for (int j = tid; j < DV / 4; j += 256) od[j] = cm[j];
}

// ---------------------------------------------------------------------------
extern "C" void kernel_launch(void* const* d_in, const int* in_sizes, int n_in,
                              void* d_out, int out_size) {
    const float* feat  = (const float*)d_in[0];  // (8,32,10,2048) f32
    const float* fm    = (const float*)d_in[1];  // (8,32,2048)    f32
    const int*   objid = (const int*)  d_in[2];  // (8,32,10,353)  i32
    const float* W     = (const float*)d_in[3];  // (2048,512)     f32
    const float* bias  = (const float*)d_in[4];  // (512,)         f32
    const float* Ao2v  = (const float*)d_in[5];  // (157,353)      f32
    float* out = (float*)d_out;                  // (8,157,2560)   f32

    k_reset<<<(B_ * NC + 255) / 256, 256>>>();
    k_cls<<<(ROWS * 32 + 255) / 256, 256>>>(objid);
    k_unique<<<B_, 384>>>();
    k_zeroF<<<dim3(NC, B_), 256>>>();
    k_scatter<<<dim3(T_, B_), 256>>>(feat);
    k_hgemm<<<dim3(DE / 32, B_), 256>>>(W);
    k_ctx<<<dim3(DV / 256, B_), 256>>>(fm);
    k_out<<<dim3(NV, B_), 256>>>(Ao2v, bias, out);
}

// round 3
// speedup vs baseline: 1.4890x; 1.4890x over previous
#include <cuda_runtime.h>
#include <cuda_bf16.h>
#include <cstddef>

constexpr int B_   = 8;
constexpr int T_   = 32;
constexpr int NN   = 10;
constexpr int DOBJ = 2048;
constexpr int NV   = 157;
constexpr int NC   = 353;
constexpr int DE   = 512;
constexpr int DV   = 2048;
constexpr int ROWS_PB = T_ * NN;         // 320 rows per batch
constexpr int ROWS = B_ * ROWS_PB;       // 2560
constexpr int OUTW = DE + DV;            // 2560
constexpr int NCAP = 320;                // max distinct classes per batch
constexpr int SLOTS = 12;                // slots per hgemm pass

// Scratch (static device globals)
__device__ float g_Fc[(size_t)B_ * NCAP * DOBJ];   // compact class-sum features
__device__ float g_H [(size_t)B_ * NCAP * DE];     // Fc @ W (active slots)
__device__ int   g_cls[ROWS];
__device__ int   g_count[B_ * NC];
__device__ int   g_classlist[B_ * NC];
__device__ int   g_sorted[B_ * ROWS_PB];           // (slot<<16)|row, sorted by slot
__device__ int   g_u[B_];
__device__ float g_ctx[B_ * DV];

// ---------------------------------------------------------------------------
// K0: temporal mean of fm_context; block(0,0) also zeros per-class counters
__global__ void k_pre(const float* __restrict__ fm) {   // grid (DV/256=8, B_), 256
    int b = blockIdx.y;
    int d = blockIdx.x * 256 + threadIdx.x;
    float s = 0.f;
    #pragma unroll
    for (int t = 0; t < T_; t++)
        s += fm[((size_t)(b * T_ + t)) * DV + d];
    g_ctx[b * DV + d] = s * (1.f / T_);
    if (blockIdx.x == 0 && blockIdx.y == 0)
        for (int i = threadIdx.x; i < B_ * NC; i += 256) g_count[i] = 0;
}

// ---------------------------------------------------------------------------
// K1: per-row class decode (last nonzero index; all-zero -> 0)
__global__ void k_cls(const int* __restrict__ obj_id) {  // 320 blocks x 256
    int gtid = blockIdx.x * blockDim.x + threadIdx.x;
    int warp = gtid >> 5;
    int lane = threadIdx.x & 31;
    if (warp >= ROWS) return;
    const int* row = obj_id + (size_t)warp * NC;
    int best = -1;
    #pragma unroll
    for (int i = lane; i < NC; i += 32)
        if (row[i] != 0) best = i;
    #pragma unroll
    for (int o = 16; o > 0; o >>= 1)
        best = max(best, __shfl_xor_sync(0xffffffffu, best, o));
    int cls = (best < 0) ? 0 : best;
    if (lane == 0) {
        g_cls[warp] = cls;
        int b = warp / ROWS_PB;
        atomicAdd(&g_count[b * NC + cls], 1);
    }
}

// ---------------------------------------------------------------------------
// K2: per-batch plan: compact class list, slot map, counting-sort rows by
// slot, zero the active regions of g_Fc and g_H.
__global__ void k_plan() {   // grid B_, block 384
    int b = blockIdx.x, tid = threadIdx.x;
    int w = tid >> 5, lane = tid & 31;
    __shared__ int wc[12], base[12], u_s;
    __shared__ int slotOf[NC];
    __shared__ int offs[NCAP];

    int cnt = (tid < NC) ? g_count[b * NC + tid] : 0;
    unsigned mask = __ballot_sync(0xffffffffu, cnt > 0);
    if (lane == 0) wc[w] = __popc(mask);
    __syncthreads();
    if (tid == 0) {
        int run = 0;
        for (int i = 0; i < 12; i++) { base[i] = run; run += wc[i]; }
        u_s = run; g_u[b] = run;
    }
    __syncthreads();
    if (cnt > 0) {
        int slot = base[w] + __popc(mask & ((1u << lane) - 1u));
        g_classlist[b * NC + slot] = tid;
        slotOf[tid] = slot;
    } else if (tid < NC) slotOf[tid] = -1;
    __syncthreads();
    int u = u_s;
    if (tid == 0) {  // slot start offsets (in class/slot order)
        int run = 0;
        for (int s = 0; s < u; s++) {
            offs[s] = run;
            run += g_count[b * NC + g_classlist[b * NC + s]];
        }
    }
    __syncthreads();
    if (tid < ROWS_PB) {  // counting sort of rows by slot
        int cls = g_cls[b * ROWS_PB + tid];
        int s = slotOf[cls];
        int pos = atomicAdd(&offs[s], 1);
        g_sorted[b * ROWS_PB + pos] = (s << 16) | tid;
    }
    // zero active scratch: u rows of Fc (2048) and H (512)
    float4* pF = (float4*)(g_Fc + (size_t)b * NCAP * DOBJ);
    for (int i = tid; i < u * (DOBJ / 4); i += 384) pF[i] = make_float4(0,0,0,0);
    float4* pH = (float4*)(g_H + (size_t)b * NCAP * DE);
    for (int i = tid; i < u * (DE / 4); i += 384) pH[i] = make_float4(0,0,0,0);
}

// ---------------------------------------------------------------------------
// K3: slot-sorted scatter: register accumulation over slot runs, atomic flush.
__global__ void k_scatter(const float* __restrict__ feat) {  // grid (4, B_), 256
    int b = blockIdx.y;
    int ch = blockIdx.x * 512;
    int tid = threadIdx.x;
    int half = tid >> 7;          // rows split in 2 halves of 160
    int l = tid & 127;            // 128 threads x float4 = 512 floats

    __shared__ int s_sorted[ROWS_PB];
    for (int i = tid; i < ROWS_PB; i += 256) s_sorted[i] = g_sorted[b * ROWS_PB + i];
    __syncthreads();

    const float* fbase = feat + (size_t)b * ROWS_PB * DOBJ + ch + l * 4;
    int r = half * 160, end = r + 160;
    float4 acc = make_float4(0,0,0,0);
    int cur = s_sorted[r] >> 16;
    #pragma unroll 4
    for (; r < end; r++) {
        int pk = s_sorted[r];
        int slot = pk >> 16, row = pk & 0xFFFF;
        if (slot != cur) {
            float* dst = g_Fc + ((size_t)b * NCAP + cur) * DOBJ + ch + l * 4;
            atomicAdd(dst + 0, acc.x); atomicAdd(dst + 1, acc.y);
            atomicAdd(dst + 2, acc.z); atomicAdd(dst + 3, acc.w);
            acc = make_float4(0,0,0,0);
            cur = slot;
        }
        float4 v = *(const float4*)(fbase + (size_t)row * DOBJ);
        acc.x += v.x; acc.y += v.y; acc.z += v.z; acc.w += v.w;
    }
    float* dst = g_Fc + ((size_t)b * NCAP + cur) * DOBJ + ch + l * 4;
    atomicAdd(dst + 0, acc.x); atomicAdd(dst + 1, acc.y);
    atomicAdd(dst + 2, acc.z); atomicAdd(dst + 3, acc.w);
}

// ---------------------------------------------------------------------------
// K4: H[b,slot,:] += Fc[b,slot,kq*512:+512] @ W[kq*512:+512,:]
// grid (DE/32=16, 4 k-quarters, B_), block 256. 12 slots per pass.
__global__ void k_hgemm(const float* __restrict__ W) {
    __shared__ float Fs[SLOTS][512];        // 24 KB
    __shared__ float red[8][SLOTS][32];     // 12 KB
    int b = blockIdx.z;
    int kq = blockIdx.y;
    int colg = blockIdx.x * 32;
    int tid = threadIdx.x, col = tid & 31, kg = tid >> 5;  // 8 kgroups of 64 k
    int u = g_u[b];

    for (int g0 = 0; g0 < u; g0 += SLOTS) {
        int ns = min(SLOTS, u - g0);
        for (int j = tid; j < SLOTS * 128; j += 256) {   // float4 units
            int s = j >> 7, kk = j & 127;
            float4 v = (s < ns)
                ? ((const float4*)(g_Fc + ((size_t)b * NCAP + g0 + s) * DOBJ + kq * 512))[kk]
                : make_float4(0,0,0,0);
            ((float4*)Fs[s])[kk] = v;
        }
        __syncthreads();

        float acc[SLOTS];
        #pragma unroll
        for (int s = 0; s < SLOTS; s++) acc[s] = 0.f;
        const float* Wp = W + ((size_t)(kq * 512 + kg * 64)) * DE + colg + col;
        #pragma unroll 4
        for (int kk = 0; kk < 64; kk += 4) {
            float w0 = Wp[(size_t)(kk + 0) * DE];
            float w1 = Wp[(size_t)(kk + 1) * DE];
            float w2 = Wp[(size_t)(kk + 2) * DE];
            float w3 = Wp[(size_t)(kk + 3) * DE];
            int kl = kg * 64 + kk;
            #pragma unroll
            for (int s = 0; s < SLOTS; s++) {
                float4 f = *(const float4*)&Fs[s][kl];
                acc[s] += f.x * w0 + f.y * w1 + f.z * w2 + f.w * w3;
            }
        }
        #pragma unroll
        for (int s = 0; s < SLOTS; s++) red[kg][s][col] = acc[s];
        __syncthreads();
        // FIX (R2 bug): grid-stride reduce — blockDim=256 < SLOTS*32=384,
        // so the old `if (tid < SLOTS*32)` dropped slots 8..11 entirely.
        for (int j = tid; j < ns * 32; j += 256) {
            int s = j >> 5, c2 = j & 31;
            float h = 0.f;
            #pragma unroll
            for (int k2 = 0; k2 < 8; k2++) h += red[k2][s][c2];
            atomicAdd(&g_H[((size_t)b * NCAP + g0 + s) * DE + colg + c2], h);
        }
        __syncthreads();
    }
}

// ---------------------------------------------------------------------------
// K5: assemble output rows
__global__ void k_out(const float* __restrict__ Ao2v,
                      const float* __restrict__ bias,
                      float* __restrict__ out) {  // grid (NV, B_), 256
    int v = blockIdx.x, b = blockIdx.y;
    int tid = threadIdx.x;
    int u = g_u[b];
    float sbv = 0.f, a0 = 0.f, a1 = 0.f;
    for (int s = 0; s < u; s++) {
        int c = g_classlist[b * NC + s];
        float a = Ao2v[(size_t)v * NC + c];
        sbv += a * (float)g_count[b * NC + c];
        const float* Hr = g_H + ((size_t)b * NCAP + s) * DE;
        a0 += a * Hr[tid];
        a1 += a * Hr[tid + 256];
    }
    const float inv = 1.f / T_;
    float* orow = out + ((size_t)b * NV + v) * OUTW;
    orow[tid]       = (a0 + sbv * bias[tid]) * inv;
    orow[tid + 256] = (a1 + sbv * bias[tid + 256]) * inv;
    const float4* cm = (const float4*)(g_ctx + (size_t)b * DV);
    float4* od = (float4*)(orow + DE);
    #pragma unroll
    for (int j = tid; j < DV / 4; j += 256) od[j] = cm[j];
}

// ---------------------------------------------------------------------------
extern "C" void kernel_launch(void* const* d_in, const int* in_sizes, int n_in,
                              void* d_out, int out_size) {
    const float* feat  = (const float*)d_in[0];
    const float* fm    = (const float*)d_in[1];
    const int*   objid = (const int*)  d_in[2];
    const float* W     = (const float*)d_in[3];
    const float* bias  = (const float*)d_in[4];
    const float* Ao2v  = (const float*)d_in[5];
    float* out = (float*)d_out;

    k_pre    <<<dim3(DV / 256, B_), 256>>>(fm);
    k_cls    <<<(ROWS * 32) / 256, 256>>>(objid);
    k_plan   <<<B_, 384>>>();
    k_scatter<<<dim3(DOBJ / 512, B_), 256>>>(feat);
    k_hgemm  <<<dim3(DE / 32, 4, B_), 256>>>(W);
    k_out    <<<dim3(NV, B_), 256>>>(Ao2v, bias, out);
}

// round 4
// speedup vs baseline: 2.2936x; 1.5404x over previous
#include <cuda_runtime.h>
#include <cuda_bf16.h>
#include <cstddef>

constexpr int B_   = 8;
constexpr int T_   = 32;
constexpr int NN   = 10;
constexpr int DOBJ = 2048;
constexpr int NV   = 157;
constexpr int NC   = 353;
constexpr int DE   = 512;
constexpr int DV   = 2048;
constexpr int ROWS_PB = T_ * NN;         // 320 rows per batch
constexpr int ROWS = B_ * ROWS_PB;       // 2560
constexpr int OUTW = DE + DV;            // 2560
constexpr int NCAP = 320;                // max distinct classes per batch
constexpr int SLOTS = 12;                // slots per hgemm pass
constexpr int RG   = 16;                 // scatter row-groups per batch
constexpr int RPG  = ROWS_PB / RG;       // 20 rows per group (10 per half)

// Scratch (static device globals; zero-initialized at load)
__device__ float g_Fc[(size_t)B_ * NCAP * DOBJ];   // compact class-sum features
__device__ float g_H [(size_t)B_ * NCAP * DE];     // Fc @ W (active slots)
__device__ int   g_cls[ROWS];
__device__ int   g_count[B_ * NC];                 // transient; re-zeroed by k_plan
__device__ int   g_cnt[B_ * NCAP];                 // compact per-slot counts
__device__ int   g_classlist[B_ * NC];
__device__ int   g_sorted[B_ * ROWS_PB];           // (slot<<16)|row, sorted by slot
__device__ int   g_u[B_];
__device__ float g_ctx[B_ * DV];

// ---------------------------------------------------------------------------
// K0: fused — blocks [0,64): temporal mean of fm_context
//             blocks [64,384): per-row class decode (warp per row)
// g_count is NOT zeroed here: k_plan restores it to zero after use, and
// device globals start zero-initialized, so it is always zero on entry.
__global__ void k_precls(const float* __restrict__ fm,
                         const int* __restrict__ obj_id) {  // grid 384, block 256
    if (blockIdx.x < 64) {
        int i = blockIdx.x * 256 + threadIdx.x;      // B_*DV = 16384
        int b = i / DV, d = i % DV;
        float s = 0.f;
        #pragma unroll
        for (int t = 0; t < T_; t++)
            s += fm[((size_t)(b * T_ + t)) * DV + d];
        g_ctx[b * DV + d] = s * (1.f / T_);
    } else {
        int blk = blockIdx.x - 64;                    // 320 blocks, 8 warps each
        int warp = blk * 8 + (threadIdx.x >> 5);      // row id 0..2559
        int lane = threadIdx.x & 31;
        const int* row = obj_id + (size_t)warp * NC;
        int best = -1;
        #pragma unroll
        for (int i = lane; i < NC; i += 32)
            if (row[i] != 0) best = i;
        #pragma unroll
        for (int o = 16; o > 0; o >>= 1)
            best = max(best, __shfl_xor_sync(0xffffffffu, best, o));
        int cls = (best < 0) ? 0 : best;
        if (lane == 0) {
            g_cls[warp] = cls;
            int b = warp / ROWS_PB;
            atomicAdd(&g_count[b * NC + cls], 1);
        }
    }
}

// ---------------------------------------------------------------------------
// K1: per-batch plan: compact class list, counting-sort rows by slot,
// compact counts, restore g_count to zero, zero active Fc/H rows.
__global__ void k_plan() {   // grid B_, block 384
    int b = blockIdx.x, tid = threadIdx.x;
    int w = tid >> 5, lane = tid & 31;
    __shared__ int wc[12], base[12], u_s;
    __shared__ int slotOf[NC];
    __shared__ int offs[NCAP];

    int cnt = (tid < NC) ? g_count[b * NC + tid] : 0;
    unsigned mask = __ballot_sync(0xffffffffu, cnt > 0);
    if (lane == 0) wc[w] = __popc(mask);
    __syncthreads();
    if (tid == 0) {
        int run = 0;
        for (int i = 0; i < 12; i++) { base[i] = run; run += wc[i]; }
        u_s = run; g_u[b] = run;
    }
    __syncthreads();
    if (cnt > 0) {
        int slot = base[w] + __popc(mask & ((1u << lane) - 1u));
        g_classlist[b * NC + slot] = tid;
        g_cnt[b * NCAP + slot] = cnt;
        slotOf[tid] = slot;
        g_count[b * NC + tid] = 0;        // restore zero state for next replay
    } else if (tid < NC) slotOf[tid] = -1;
    __syncthreads();
    int u = u_s;
    if (tid == 0) {  // slot start offsets
        int run = 0;
        for (int s = 0; s < u; s++) { offs[s] = run; run += g_cnt[b * NCAP + s]; }
    }
    __syncthreads();
    if (tid < ROWS_PB) {  // counting sort of rows by slot
        int cls = g_cls[b * ROWS_PB + tid];
        int s = slotOf[cls];
        int pos = atomicAdd(&offs[s], 1);
        g_sorted[b * ROWS_PB + pos] = (s << 16) | tid;
    }
    // zero active scratch: u rows of Fc (2048) and H (512)
    float4* pF = (float4*)(g_Fc + (size_t)b * NCAP * DOBJ);
    for (int i = tid; i < u * (DOBJ / 4); i += 384) pF[i] = make_float4(0,0,0,0);
    float4* pH = (float4*)(g_H + (size_t)b * NCAP * DE);
    for (int i = tid; i < u * (DE / 4); i += 384) pH[i] = make_float4(0,0,0,0);
}

// ---------------------------------------------------------------------------
// K2: slot-sorted scatter, 16 row-groups per batch for parallelism.
// Register accumulation over slot runs; atomic flush on run boundaries
// (runs crossing row-group edges are merged by the atomics).
__global__ void k_scatter(const float* __restrict__ feat) {
    // grid (DOBJ/512=4, RG=16, B_), block 256
    int b = blockIdx.z, rg = blockIdx.y;
    int ch = blockIdx.x * 512;
    int tid = threadIdx.x;
    int half = tid >> 7;          // 2 halves of RPG/2 = 10 rows
    int l = tid & 127;            // 128 threads x float4 = 512 floats

    __shared__ int s_sorted[RPG];
    if (tid < RPG) s_sorted[tid] = g_sorted[b * ROWS_PB + rg * RPG + tid];
    __syncthreads();

    const float* fbase = feat + (size_t)b * ROWS_PB * DOBJ + ch + l * 4;
    int r = half * (RPG / 2), end = r + (RPG / 2);
    float4 acc = make_float4(0, 0, 0, 0);
    int cur = s_sorted[r] >> 16;
    #pragma unroll
    for (; r < end; r++) {
        int pk = s_sorted[r];
        int slot = pk >> 16, row = pk & 0xFFFF;
        if (slot != cur) {
            float* dst = g_Fc + ((size_t)b * NCAP + cur) * DOBJ + ch + l * 4;
            atomicAdd(dst + 0, acc.x); atomicAdd(dst + 1, acc.y);
            atomicAdd(dst + 2, acc.z); atomicAdd(dst + 3, acc.w);
            acc = make_float4(0, 0, 0, 0);
            cur = slot;
        }
        float4 v = *(const float4*)(fbase + (size_t)row * DOBJ);
        acc.x += v.x; acc.y += v.y; acc.z += v.z; acc.w += v.w;
    }
    float* dst = g_Fc + ((size_t)b * NCAP + cur) * DOBJ + ch + l * 4;
    atomicAdd(dst + 0, acc.x); atomicAdd(dst + 1, acc.y);
    atomicAdd(dst + 2, acc.z); atomicAdd(dst + 3, acc.w);
}

// ---------------------------------------------------------------------------
// K3: H[b,slot,:] += Fc[b,slot,kq*512:+512] @ W[kq*512:+512,:]
// grid (DE/32=16, 4 k-quarters, B_), block 256. 12 slots per pass.
__global__ void k_hgemm(const float* __restrict__ W) {
    __shared__ float Fs[SLOTS][512];        // 24 KB
    __shared__ float red[8][SLOTS][32];     // 12 KB
    int b = blockIdx.z;
    int kq = blockIdx.y;
    int colg = blockIdx.x * 32;
    int tid = threadIdx.x, col = tid & 31, kg = tid >> 5;  // 8 kgroups of 64 k
    int u = g_u[b];

    for (int g0 = 0; g0 < u; g0 += SLOTS) {
        int ns = min(SLOTS, u - g0);
        for (int j = tid; j < SLOTS * 128; j += 256) {   // float4 units
            int s = j >> 7, kk = j & 127;
            float4 v = (s < ns)
                ? ((const float4*)(g_Fc + ((size_t)b * NCAP + g0 + s) * DOBJ + kq * 512))[kk]
                : make_float4(0, 0, 0, 0);
            ((float4*)Fs[s])[kk] = v;
        }
        __syncthreads();

        float acc[SLOTS];
        #pragma unroll
        for (int s = 0; s < SLOTS; s++) acc[s] = 0.f;
        const float* Wp = W + ((size_t)(kq * 512 + kg * 64)) * DE + colg + col;
        #pragma unroll 4
        for (int kk = 0; kk < 64; kk += 4) {
            float w0 = Wp[(size_t)(kk + 0) * DE];
            float w1 = Wp[(size_t)(kk + 1) * DE];
            float w2 = Wp[(size_t)(kk + 2) * DE];
            float w3 = Wp[(size_t)(kk + 3) * DE];
            int kl = kg * 64 + kk;
            #pragma unroll
            for (int s = 0; s < SLOTS; s++) {
                float4 f = *(const float4*)&Fs[s][kl];
                acc[s] += f.x * w0 + f.y * w1 + f.z * w2 + f.w * w3;
            }
        }
        #pragma unroll
        for (int s = 0; s < SLOTS; s++) red[kg][s][col] = acc[s];
        __syncthreads();
        for (int j = tid; j < ns * 32; j += 256) {     // grid-stride (ns*32 can be >256)
            int s = j >> 5, c2 = j & 31;
            float h = 0.f;
            #pragma unroll
            for (int k2 = 0; k2 < 8; k2++) h += red[k2][s][c2];
            atomicAdd(&g_H[((size_t)b * NCAP + g0 + s) * DE + colg + c2], h);
        }
        __syncthreads();
    }
}

// ---------------------------------------------------------------------------
// K4: assemble output rows
__global__ void k_out(const float* __restrict__ Ao2v,
                      const float* __restrict__ bias,
                      float* __restrict__ out) {  // grid (NV, B_), 256
    int v = blockIdx.x, b = blockIdx.y;
    int tid = threadIdx.x;
    int u = g_u[b];
    float sbv = 0.f, a0 = 0.f, a1 = 0.f;
    for (int s = 0; s < u; s++) {
        int c = g_classlist[b * NC + s];
        float a = Ao2v[(size_t)v * NC + c];
        sbv += a * (float)g_cnt[b * NCAP + s];
        const float* Hr = g_H + ((size_t)b * NCAP + s) * DE;
        a0 += a * Hr[tid];
        a1 += a * Hr[tid + 256];
    }
    const float inv = 1.f / T_;
    float* orow = out + ((size_t)b * NV + v) * OUTW;
    orow[tid]       = (a0 + sbv * bias[tid]) * inv;
    orow[tid + 256] = (a1 + sbv * bias[tid + 256]) * inv;
    const float4* cm = (const float4*)(g_ctx + (size_t)b * DV);
    float4* od = (float4*)(orow + DE);
    #pragma unroll
    for (int j = tid; j < DV / 4; j += 256) od[j] = cm[j];
}

// ---------------------------------------------------------------------------
extern "C" void kernel_launch(void* const* d_in, const int* in_sizes, int n_in,
                              void* d_out, int out_size) {
    const float* feat  = (const float*)d_in[0];
    const float* fm    = (const float*)d_in[1];
    const int*   objid = (const int*)  d_in[2];
    const float* W     = (const float*)d_in[3];
    const float* bias  = (const float*)d_in[4];
    const float* Ao2v  = (const float*)d_in[5];
    float* out = (float*)d_out;

    k_precls <<<384, 256>>>(fm, objid);
    k_plan   <<<B_, 384>>>();
    k_scatter<<<dim3(DOBJ / 512, RG, B_), 256>>>(feat);
    k_hgemm  <<<dim3(DE / 32, 4, B_), 256>>>(W);
    k_out    <<<dim3(NV, B_), 256>>>(Ao2v, bias, out);
}

// round 5
// speedup vs baseline: 2.4295x; 1.0593x over previous
#include <cuda_runtime.h>
#include <cuda_bf16.h>
#include <cstddef>

constexpr int B_   = 8;
constexpr int T_   = 32;
constexpr int NN   = 10;
constexpr int DOBJ = 2048;
constexpr int NV   = 157;
constexpr int NC   = 353;
constexpr int DE   = 512;
constexpr int DV   = 2048;
constexpr int ROWS_PB = T_ * NN;         // 320 rows per batch
constexpr int ROWS = B_ * ROWS_PB;       // 2560
constexpr int OUTW = DE + DV;            // 2560
constexpr int NCAP = 320;                // max distinct classes per batch
constexpr int SLOTS = 12;                // slots per hgemm pass
constexpr int RG   = 16;                 // scatter row-groups per batch
constexpr int RPG  = ROWS_PB / RG;       // 20 rows per group (10 per half)

// Scratch (static device globals; zero-initialized at load)
__device__ float g_Fc[(size_t)B_ * NCAP * DOBJ];   // compact class-sum features
__device__ float g_H [(size_t)B_ * NCAP * DE];     // Fc @ W (active slots)
__device__ int   g_cls[ROWS];
__device__ int   g_count[B_ * NC];                 // transient; re-zeroed by k_plan
__device__ int   g_cnt[B_ * NCAP];                 // compact per-slot counts
__device__ int   g_classlist[B_ * NC];
__device__ int   g_sorted[B_ * ROWS_PB];           // (slot<<16)|row, sorted by slot
__device__ int   g_u[B_];
__device__ float g_ctx[B_ * DV];

// ---------------------------------------------------------------------------
// K0: fused — blocks [0,64): temporal mean of fm_context
//             blocks [64,384): per-row class decode (warp per row)
__global__ void k_precls(const float* __restrict__ fm,
                         const int* __restrict__ obj_id) {  // grid 384, block 256
    if (blockIdx.x < 64) {
        int i = blockIdx.x * 256 + threadIdx.x;      // B_*DV = 16384
        int b = i / DV, d = i % DV;
        float s = 0.f;
        #pragma unroll
        for (int t = 0; t < T_; t++)
            s += fm[((size_t)(b * T_ + t)) * DV + d];
        g_ctx[b * DV + d] = s * (1.f / T_);
    } else {
        int blk = blockIdx.x - 64;                    // 320 blocks, 8 warps each
        int warp = blk * 8 + (threadIdx.x >> 5);      // row id 0..2559
        int lane = threadIdx.x & 31;
        const int* row = obj_id + (size_t)warp * NC;
        int best = -1;
        #pragma unroll
        for (int i = lane; i < NC; i += 32)
            if (row[i] != 0) best = i;
        #pragma unroll
        for (int o = 16; o > 0; o >>= 1)
            best = max(best, __shfl_xor_sync(0xffffffffu, best, o));
        int cls = (best < 0) ? 0 : best;
        if (lane == 0) {
            g_cls[warp] = cls;
            int b = warp / ROWS_PB;
            atomicAdd(&g_count[b * NC + cls], 1);
        }
    }
}

// ---------------------------------------------------------------------------
// K1: per-batch plan: compact class list, counting-sort rows by slot,
// compact counts, restore g_count to zero, zero active Fc/H rows.
__global__ void k_plan() {   // grid B_, block 384
    int b = blockIdx.x, tid = threadIdx.x;
    int w = tid >> 5, lane = tid & 31;
    __shared__ int wc[12], base[12], u_s;
    __shared__ int slotOf[NC];
    __shared__ int offs[NCAP];

    int cnt = (tid < NC) ? g_count[b * NC + tid] : 0;
    unsigned mask = __ballot_sync(0xffffffffu, cnt > 0);
    if (lane == 0) wc[w] = __popc(mask);
    __syncthreads();
    if (tid == 0) {
        int run = 0;
        for (int i = 0; i < 12; i++) { base[i] = run; run += wc[i]; }
        u_s = run; g_u[b] = run;
    }
    __syncthreads();
    if (cnt > 0) {
        int slot = base[w] + __popc(mask & ((1u << lane) - 1u));
        g_classlist[b * NC + slot] = tid;
        g_cnt[b * NCAP + slot] = cnt;
        slotOf[tid] = slot;
        g_count[b * NC + tid] = 0;        // restore zero state for next replay
    } else if (tid < NC) slotOf[tid] = -1;
    __syncthreads();
    int u = u_s;
    if (tid == 0) {  // slot start offsets
        int run = 0;
        for (int s = 0; s < u; s++) { offs[s] = run; run += g_cnt[b * NCAP + s]; }
    }
    __syncthreads();
    if (tid < ROWS_PB) {  // counting sort of rows by slot
        int cls = g_cls[b * ROWS_PB + tid];
        int s = slotOf[cls];
        int pos = atomicAdd(&offs[s], 1);
        g_sorted[b * ROWS_PB + pos] = (s << 16) | tid;
    }
    // zero active scratch: u rows of Fc (2048) and H (512)
    float4* pF = (float4*)(g_Fc + (size_t)b * NCAP * DOBJ);
    for (int i = tid; i < u * (DOBJ / 4); i += 384) pF[i] = make_float4(0,0,0,0);
    float4* pH = (float4*)(g_H + (size_t)b * NCAP * DE);
    for (int i = tid; i < u * (DE / 4); i += 384) pH[i] = make_float4(0,0,0,0);
}

// ---------------------------------------------------------------------------
// K2: slot-sorted scatter, 16 row-groups per batch for parallelism.
__global__ void k_scatter(const float* __restrict__ feat) {
    // grid (DOBJ/512=4, RG=16, B_), block 256
    int b = blockIdx.z, rg = blockIdx.y;
    int ch = blockIdx.x * 512;
    int tid = threadIdx.x;
    int half = tid >> 7;          // 2 halves of RPG/2 = 10 rows
    int l = tid & 127;            // 128 threads x float4 = 512 floats

    __shared__ int s_sorted[RPG];
    if (tid < RPG) s_sorted[tid] = g_sorted[b * ROWS_PB + rg * RPG + tid];
    __syncthreads();

    const float* fbase = feat + (size_t)b * ROWS_PB * DOBJ + ch + l * 4;
    int r = half * (RPG / 2), end = r + (RPG / 2);
    float4 acc = make_float4(0, 0, 0, 0);
    int cur = s_sorted[r] >> 16;
    #pragma unroll
    for (; r < end; r++) {
        int pk = s_sorted[r];
        int slot = pk >> 16, row = pk & 0xFFFF;
        if (slot != cur) {
            float* dst = g_Fc + ((size_t)b * NCAP + cur) * DOBJ + ch + l * 4;
            atomicAdd(dst + 0, acc.x); atomicAdd(dst + 1, acc.y);
            atomicAdd(dst + 2, acc.z); atomicAdd(dst + 3, acc.w);
            acc = make_float4(0, 0, 0, 0);
            cur = slot;
        }
        float4 v = *(const float4*)(fbase + (size_t)row * DOBJ);
        acc.x += v.x; acc.y += v.y; acc.z += v.z; acc.w += v.w;
    }
    float* dst = g_Fc + ((size_t)b * NCAP + cur) * DOBJ + ch + l * 4;
    atomicAdd(dst + 0, acc.x); atomicAdd(dst + 1, acc.y);
    atomicAdd(dst + 2, acc.z); atomicAdd(dst + 3, acc.w);
}

// ---------------------------------------------------------------------------
// K3: H[b,slot,:] += Fc[b,slot,kq*512:+512] @ W[kq*512:+512,:]
// grid (DE/32=16 colg, 4 kq, B_), block 256.
// Thread tile: 12 slots x 2 cols (float2 W loads) -> 96 FFMA per 16 mem-instr.
// k mapping: thread (cp, kg) handles k = kg*4 + i*64 + [0,4), i in [0,8):
// the two kg's of a warp read ADJACENT 16B of Fs -> conflict-free broadcast.
__global__ void k_hgemm(const float* __restrict__ W) {
    __shared__ float Fs[SLOTS][512];          // 24 KB
    __shared__ float red[16][SLOTS][32];      // 24 KB
    int b = blockIdx.z;
    int kq = blockIdx.y;
    int colg = blockIdx.x * 32;
    int tid = threadIdx.x;
    int cp = tid & 15;            // colpair -> cols colg + 2cp, 2cp+1
    int kg = tid >> 4;            // 0..15
    int u = g_u[b];

    for (int g0 = 0; g0 < u; g0 += SLOTS) {
        int ns = min(SLOTS, u - g0);
        for (int j = tid; j < SLOTS * 128; j += 256) {   // float4 units
            int s = j >> 7, kk = j & 127;
            float4 v = (s < ns)
                ? ((const float4*)(g_Fc + ((size_t)b * NCAP + g0 + s) * DOBJ + kq * 512))[kk]
                : make_float4(0, 0, 0, 0);
            ((float4*)Fs[s])[kk] = v;
        }
        __syncthreads();

        float2 acc[SLOTS];
        #pragma unroll
        for (int s = 0; s < SLOTS; s++) acc[s] = make_float2(0.f, 0.f);

        const float* Wp = W + ((size_t)(kq * 512)) * DE + colg + cp * 2;
        #pragma unroll 2
        for (int i = 0; i < 8; i++) {
            int kbase = kg * 4 + i * 64;
            const float* Wk = Wp + (size_t)kbase * DE;
            float2 w0 = *(const float2*)&Wk[0 * DE];
            float2 w1 = *(const float2*)&Wk[1 * DE];
            float2 w2 = *(const float2*)&Wk[2 * DE];
            float2 w3 = *(const float2*)&Wk[3 * DE];
            #pragma unroll
            for (int s = 0; s < SLOTS; s++) {
                float4 f = *(const float4*)&Fs[s][kbase];
                acc[s].x += f.x * w0.x + f.y * w1.x + f.z * w2.x + f.w * w3.x;
                acc[s].y += f.x * w0.y + f.y * w1.y + f.z * w2.y + f.w * w3.y;
            }
        }

        #pragma unroll
        for (int s = 0; s < SLOTS; s++) {
            red[kg][s][cp * 2]     = acc[s].x;
            red[kg][s][cp * 2 + 1] = acc[s].y;
        }
        __syncthreads();
        for (int j = tid; j < ns * 32; j += 256) {   // grid-stride (ns*32 can be >256)
            int s = j >> 5, c2 = j & 31;
            float h = 0.f;
            #pragma unroll
            for (int k2 = 0; k2 < 16; k2++) h += red[k2][s][c2];
            atomicAdd(&g_H[((size_t)b * NCAP + g0 + s) * DE + colg + c2], h);
        }
        __syncthreads();
    }
}

// ---------------------------------------------------------------------------
// K4: assemble output rows
__global__ void k_out(const float* __restrict__ Ao2v,
                      const float* __restrict__ bias,
                      float* __restrict__ out) {  // grid (NV, B_), 256
    int v = blockIdx.x, b = blockIdx.y;
    int tid = threadIdx.x;
    int u = g_u[b];
    float sbv = 0.f, a0 = 0.f, a1 = 0.f;
    for (int s = 0; s < u; s++) {
        int c = g_classlist[b * NC + s];
        float a = Ao2v[(size_t)v * NC + c];
        sbv += a * (float)g_cnt[b * NCAP + s];
        const float* Hr = g_H + ((size_t)b * NCAP + s) * DE;
        a0 += a * Hr[tid];
        a1 += a * Hr[tid + 256];
    }
    const float inv = 1.f / T_;
    float* orow = out + ((size_t)b * NV + v) * OUTW;
    orow[tid]       = (a0 + sbv * bias[tid]) * inv;
    orow[tid + 256] = (a1 + sbv * bias[tid + 256]) * inv;
    const float4* cm = (const float4*)(g_ctx + (size_t)b * DV);
    float4* od = (float4*)(orow + DE);
    #pragma unroll
    for (int j = tid; j < DV / 4; j += 256) od[j] = cm[j];
}

// ---------------------------------------------------------------------------
extern "C" void kernel_launch(void* const* d_in, const int* in_sizes, int n_in,
                              void* d_out, int out_size) {
    const float* feat  = (const float*)d_in[0];
    const float* fm    = (const float*)d_in[1];
    const int*   objid = (const int*)  d_in[2];
    const float* W     = (const float*)d_in[3];
    const float* bias  = (const float*)d_in[4];
    const float* Ao2v  = (const float*)d_in[5];
    float* out = (float*)d_out;

    k_precls <<<384, 256>>>(fm, objid);
    k_plan   <<<B_, 384>>>();
    k_scatter<<<dim3(DOBJ / 512, RG, B_), 256>>>(feat);
    k_hgemm  <<<dim3(DE / 32, 4, B_), 256>>>(W);
    k_out    <<<dim3(NV, B_), 256>>>(Ao2v, bias, out);
}

// round 6
// speedup vs baseline: 2.5641x; 1.0554x over previous
#include <cuda_runtime.h>
#include <cuda_bf16.h>
#include <cstddef>

constexpr int B_   = 8;
constexpr int T_   = 32;
constexpr int NN   = 10;
constexpr int DOBJ = 2048;
constexpr int NV   = 157;
constexpr int NC   = 353;
constexpr int DE   = 512;
constexpr int DV   = 2048;
constexpr int ROWS_PB = T_ * NN;         // 320 rows per batch
constexpr int ROWS = B_ * ROWS_PB;       // 2560
constexpr int OUTW = DE + DV;            // 2560
constexpr int NCAP = 320;                // max distinct classes per batch
constexpr int SLOTS = 12;                // slots per hgemm pass
constexpr int RG   = 16;                 // scatter row-groups per batch
constexpr int RPG  = ROWS_PB / RG;       // 20 rows per group (10 per half)
constexpr int KQ   = 8;                  // hgemm k-chunks (256 k each)

// Scratch (static device globals; zero-initialized at load)
__device__ float g_Fc[(size_t)B_ * NCAP * DOBJ];   // compact class-sum features
__device__ float g_H [(size_t)B_ * NCAP * DE];     // Fc @ W (active slots)
__device__ int   g_cls[ROWS];
__device__ int   g_count[B_ * NC];                 // transient; re-zeroed by k_plan
__device__ int   g_cnt[B_ * NCAP];                 // compact per-slot counts
__device__ int   g_classlist[B_ * NC];
__device__ int   g_sorted[B_ * ROWS_PB];           // (slot<<16)|row, sorted by slot
__device__ int   g_u[B_];
__device__ float g_ctx[B_ * DV];

// ---------------------------------------------------------------------------
// K0: fused — blocks [0,64): temporal mean of fm_context
//             blocks [64,384): per-row class decode (warp per row)
__global__ void k_precls(const float* __restrict__ fm,
                         const int* __restrict__ obj_id) {  // grid 384, block 256
    if (blockIdx.x < 64) {
        int i = blockIdx.x * 256 + threadIdx.x;      // B_*DV = 16384
        int b = i / DV, d = i % DV;
        float s = 0.f;
        #pragma unroll
        for (int t = 0; t < T_; t++)
            s += fm[((size_t)(b * T_ + t)) * DV + d];
        g_ctx[b * DV + d] = s * (1.f / T_);
    } else {
        int blk = blockIdx.x - 64;                    // 320 blocks, 8 warps each
        int warp = blk * 8 + (threadIdx.x >> 5);      // row id 0..2559
        int lane = threadIdx.x & 31;
        const int* row = obj_id + (size_t)warp * NC;
        int best = -1;
        #pragma unroll
        for (int i = lane; i < NC; i += 32)
            if (row[i] != 0) best = i;
        #pragma unroll
        for (int o = 16; o > 0; o >>= 1)
            best = max(best, __shfl_xor_sync(0xffffffffu, best, o));
        int cls = (best < 0) ? 0 : best;
        if (lane == 0) {
            g_cls[warp] = cls;
            int b = warp / ROWS_PB;
            atomicAdd(&g_count[b * NC + cls], 1);
        }
    }
}

// ---------------------------------------------------------------------------
// K1: per-batch plan: compact class list, counting-sort rows by slot,
// compact counts, restore g_count to zero, zero active Fc/H rows.
__global__ void k_plan() {   // grid B_, block 384
    int b = blockIdx.x, tid = threadIdx.x;
    int w = tid >> 5, lane = tid & 31;
    __shared__ int wc[12], base[12], u_s;
    __shared__ int slotOf[NC];
    __shared__ int offs[NCAP];

    int cnt = (tid < NC) ? g_count[b * NC + tid] : 0;
    unsigned mask = __ballot_sync(0xffffffffu, cnt > 0);
    if (lane == 0) wc[w] = __popc(mask);
    __syncthreads();
    if (tid == 0) {
        int run = 0;
        for (int i = 0; i < 12; i++) { base[i] = run; run += wc[i]; }
        u_s = run; g_u[b] = run;
    }
    __syncthreads();
    if (cnt > 0) {
        int slot = base[w] + __popc(mask & ((1u << lane) - 1u));
        g_classlist[b * NC + slot] = tid;
        g_cnt[b * NCAP + slot] = cnt;
        slotOf[tid] = slot;
        g_count[b * NC + tid] = 0;        // restore zero state for next replay
    } else if (tid < NC) slotOf[tid] = -1;
    __syncthreads();
    int u = u_s;
    if (tid == 0) {  // slot start offsets
        int run = 0;
        for (int s = 0; s < u; s++) { offs[s] = run; run += g_cnt[b * NCAP + s]; }
    }
    __syncthreads();
    if (tid < ROWS_PB) {  // counting sort of rows by slot
        int cls = g_cls[b * ROWS_PB + tid];
        int s = slotOf[cls];
        int pos = atomicAdd(&offs[s], 1);
        g_sorted[b * ROWS_PB + pos] = (s << 16) | tid;
    }
    // zero active scratch: u rows of Fc (2048) and H (512)
    float4* pF = (float4*)(g_Fc + (size_t)b * NCAP * DOBJ);
    for (int i = tid; i < u * (DOBJ / 4); i += 384) pF[i] = make_float4(0,0,0,0);
    float4* pH = (float4*)(g_H + (size_t)b * NCAP * DE);
    for (int i = tid; i < u * (DE / 4); i += 384) pH[i] = make_float4(0,0,0,0);
}

// ---------------------------------------------------------------------------
// K2: slot-sorted scatter, 16 row-groups per batch for parallelism.
__global__ void k_scatter(const float* __restrict__ feat) {
    // grid (DOBJ/512=4, RG=16, B_), block 256
    int b = blockIdx.z, rg = blockIdx.y;
    int ch = blockIdx.x * 512;
    int tid = threadIdx.x;
    int half = tid >> 7;          // 2 halves of RPG/2 = 10 rows
    int l = tid & 127;            // 128 threads x float4 = 512 floats

    __shared__ int s_sorted[RPG];
    if (tid < RPG) s_sorted[tid] = g_sorted[b * ROWS_PB + rg * RPG + tid];
    __syncthreads();

    const float* fbase = feat + (size_t)b * ROWS_PB * DOBJ + ch + l * 4;
    int r = half * (RPG / 2), end = r + (RPG / 2);
    float4 acc = make_float4(0, 0, 0, 0);
    int cur = s_sorted[r] >> 16;
    #pragma unroll
    for (; r < end; r++) {
        int pk = s_sorted[r];
        int slot = pk >> 16, row = pk & 0xFFFF;
        if (slot != cur) {
            float* dst = g_Fc + ((size_t)b * NCAP + cur) * DOBJ + ch + l * 4;
            atomicAdd(dst + 0, acc.x); atomicAdd(dst + 1, acc.y);
            atomicAdd(dst + 2, acc.z); atomicAdd(dst + 3, acc.w);
            acc = make_float4(0, 0, 0, 0);
            cur = slot;
        }
        float4 v = *(const float4*)(fbase + (size_t)row * DOBJ);
        acc.x += v.x; acc.y += v.y; acc.z += v.z; acc.w += v.w;
    }
    float* dst = g_Fc + ((size_t)b * NCAP + cur) * DOBJ + ch + l * 4;
    atomicAdd(dst + 0, acc.x); atomicAdd(dst + 1, acc.y);
    atomicAdd(dst + 2, acc.z); atomicAdd(dst + 3, acc.w);
}

// ---------------------------------------------------------------------------
// K3: H[b,slot,:] += Fc[b,slot,kq*256:+256] @ W[kq*256:+256,:]
// grid (DE/32=16 colg, KQ=8, B_), block 128 (cp 16 x kg 8).
// Thread tile: 12 slots x 2 cols; manual W register prefetch pipeline.
__global__ void k_hgemm(const float* __restrict__ W) {
    __shared__ float Fs[SLOTS][256];          // 12 KB
    __shared__ float red[8][SLOTS][32];       // 12 KB
    int b = blockIdx.z;
    int kq = blockIdx.y;
    int colg = blockIdx.x * 32;
    int tid = threadIdx.x;
    int cp = tid & 15;            // colpair -> cols colg + 2cp, 2cp+1
    int kg = tid >> 4;            // 0..7
    int u = g_u[b];

    for (int g0 = 0; g0 < u; g0 += SLOTS) {
        int ns = min(SLOTS, u - g0);
        for (int j = tid; j < SLOTS * 64; j += 128) {   // float4 units
            int s = j >> 6, kk = j & 63;
            float4 v = (s < ns)
                ? ((const float4*)(g_Fc + ((size_t)b * NCAP + g0 + s) * DOBJ + kq * 256))[kk]
                : make_float4(0, 0, 0, 0);
            ((float4*)Fs[s])[kk] = v;
        }
        __syncthreads();

        float2 acc[SLOTS];
        #pragma unroll
        for (int s = 0; s < SLOTS; s++) acc[s] = make_float2(0.f, 0.f);

        // k handled by this thread: kbase = kg*4 + i*32, i in [0,8)
        const float* Wbase = W + ((size_t)(kq * 256 + kg * 4)) * DE + colg + cp * 2;
        float2 w0 = *(const float2*)&Wbase[0 * DE];
        float2 w1 = *(const float2*)&Wbase[1 * DE];
        float2 w2 = *(const float2*)&Wbase[2 * DE];
        float2 w3 = *(const float2*)&Wbase[3 * DE];
        #pragma unroll
        for (int i = 0; i < 8; i++) {
            float2 n0, n1, n2, n3;
            if (i < 7) {                       // prefetch next iteration's W
                const float* Wn = Wbase + (size_t)(i + 1) * 32 * DE;
                n0 = *(const float2*)&Wn[0 * DE];
                n1 = *(const float2*)&Wn[1 * DE];
                n2 = *(const float2*)&Wn[2 * DE];
                n3 = *(const float2*)&Wn[3 * DE];
            }
            int kbase = kg * 4 + i * 32;
            #pragma unroll
            for (int s = 0; s < SLOTS; s++) {
                float4 f = *(const float4*)&Fs[s][kbase];
                acc[s].x += f.x * w0.x + f.y * w1.x + f.z * w2.x + f.w * w3.x;
                acc[s].y += f.x * w0.y + f.y * w1.y + f.z * w2.y + f.w * w3.y;
            }
            w0 = n0; w1 = n1; w2 = n2; w3 = n3;
        }

        #pragma unroll
        for (int s = 0; s < SLOTS; s++) {
            red[kg][s][cp * 2]     = acc[s].x;
            red[kg][s][cp * 2 + 1] = acc[s].y;
        }
        __syncthreads();
        for (int j = tid; j < ns * 32; j += 128) {
            int s = j >> 5, c2 = j & 31;
            float h = 0.f;
            #pragma unroll
            for (int k2 = 0; k2 < 8; k2++) h += red[k2][s][c2];
            atomicAdd(&g_H[((size_t)b * NCAP + g0 + s) * DE + colg + c2], h);
        }
        __syncthreads();
    }
}

// ---------------------------------------------------------------------------
// K4: assemble output rows
__global__ void k_out(const float* __restrict__ Ao2v,
                      const float* __restrict__ bias,
                      float* __restrict__ out) {  // grid (NV, B_), 256
    int v = blockIdx.x, b = blockIdx.y;
    int tid = threadIdx.x;
    int u = g_u[b];
    float sbv = 0.f, a0 = 0.f, a1 = 0.f;
    for (int s = 0; s < u; s++) {
        int c = g_classlist[b * NC + s];
        float a = Ao2v[(size_t)v * NC + c];
        sbv += a * (float)g_cnt[b * NCAP + s];
        const float* Hr = g_H + ((size_t)b * NCAP + s) * DE;
        a0 += a * Hr[tid];
        a1 += a * Hr[tid + 256];
    }
    const float inv = 1.f / T_;
    float* orow = out + ((size_t)b * NV + v) * OUTW;
    orow[tid]       = (a0 + sbv * bias[tid]) * inv;
    orow[tid + 256] = (a1 + sbv * bias[tid + 256]) * inv;
    const float4* cm = (const float4*)(g_ctx + (size_t)b * DV);
    float4* od = (float4*)(orow + DE);
    #pragma unroll
    for (int j = tid; j < DV / 4; j += 256) od[j] = cm[j];
}

// ---------------------------------------------------------------------------
extern "C" void kernel_launch(void* const* d_in, const int* in_sizes, int n_in,
                              void* d_out, int out_size) {
    const float* feat  = (const float*)d_in[0];
    const float* fm    = (const float*)d_in[1];
    const int*   objid = (const int*)  d_in[2];
    const float* W     = (const float*)d_in[3];
    const float* bias  = (const float*)d_in[4];
    const float* Ao2v  = (const float*)d_in[5];
    float* out = (float*)d_out;

    k_precls <<<384, 256>>>(fm, objid);
    k_plan   <<<B_, 384>>>();
    k_scatter<<<dim3(DOBJ / 512, RG, B_), 256>>>(feat);
    k_hgemm  <<<dim3(DE / 32, KQ, B_), 128>>>(W);
    k_out    <<<dim3(NV, B_), 256>>>(Ao2v, bias, out);
}